// round 2
// baseline (speedup 1.0000x reference)
#include <cuda_runtime.h>

// Problem constants (fixed shapes from reference_code)
#define E_    3
#define QE_   60000
#define P_    40
#define H_    20
#define NIMG_ 1800
#define Q_    (E_ * QE_)        // 180000 atoms
#define NNZ_  14400000
#define AB    256               // atoms per block (histogram/MLP blocking)
#define NB    704               // ceil(Q_/AB) = 704 (704*256 = 180224)

// Scratch (static device globals — sanctioned; no runtime allocation)
__device__ float g_dE[(size_t)Q_ * P_];        // dE/dFP in SORTED atom order, 28.8 MB
__device__ int   g_hist[(size_t)NIMG_ * NB];   // per-(key,block) counts -> exclusive offsets
__device__ int   g_key_total[NIMG_];
__device__ int   g_key_base[NIMG_];

// ---------------------------------------------------------------------------
__global__ void k_zero(float* __restrict__ out, int n) {
    int i = blockIdx.x * blockDim.x + threadIdx.x;
    if (i < n) out[i] = 0.0f;
}

// ---------------------------------------------------------------------------
// Per-block histogram of image_idx (basis of the stable counting sort)
// ---------------------------------------------------------------------------
__global__ void k_hist(const int* __restrict__ idx) {
    __shared__ int h[NIMG_];
    for (int k = threadIdx.x; k < NIMG_; k += blockDim.x) h[k] = 0;
    __syncthreads();
    int a = blockIdx.x * AB + threadIdx.x;
    if (a < Q_) atomicAdd(&h[idx[a]], 1);
    __syncthreads();
    for (int k = threadIdx.x; k < NIMG_; k += blockDim.x)
        g_hist[(size_t)k * NB + blockIdx.x] = h[k];
}

// ---------------------------------------------------------------------------
// For each key: exclusive scan of counts across blocks; emit per-key totals.
// ---------------------------------------------------------------------------
__global__ void k_scan_blocks() {
    __shared__ int s[1024];
    int k = blockIdx.x, t = threadIdx.x;
    int v = (t < NB) ? g_hist[(size_t)k * NB + t] : 0;
    s[t] = v;
    __syncthreads();
    for (int off = 1; off < 1024; off <<= 1) {
        int x = (t >= off) ? s[t - off] : 0;
        __syncthreads();
        s[t] += x;
        __syncthreads();
    }
    if (t < NB) g_hist[(size_t)k * NB + t] = s[t] - v;   // exclusive
    if (t == NB - 1) g_key_total[k] = s[t];
}

// ---------------------------------------------------------------------------
// Exclusive scan over the 1800 key totals -> key base offsets.
// ---------------------------------------------------------------------------
__global__ void k_scan_keys() {
    __shared__ int s[1024];
    int t = threadIdx.x;
    int i0 = 2 * t, i1 = 2 * t + 1;
    int v0 = (i0 < NIMG_) ? g_key_total[i0] : 0;
    int v1 = (i1 < NIMG_) ? g_key_total[i1] : 0;
    int p = v0 + v1;
    s[t] = p;
    __syncthreads();
    for (int off = 1; off < 1024; off <<= 1) {
        int x = (t >= off) ? s[t - off] : 0;
        __syncthreads();
        s[t] += x;
        __syncthreads();
    }
    int excl = s[t] - p;
    if (i0 < NIMG_) g_key_base[i0] = excl;
    if (i1 < NIMG_) g_key_base[i1] = excl + v0;
}

// ---------------------------------------------------------------------------
// Fused: stable local rank + MLP forward + input-gradient + energy scatter.
// Register-array discipline: every thread-local array (h1/g2/g1, 20 floats)
// is indexed ONLY inside fully-unrolled constant-trip loops so ptxas keeps
// them in registers (0 B local memory). The P_=40 input is STREAMED (rolled
// loop, scalar) — never buffered — since backward never needs x.
// ---------------------------------------------------------------------------
__global__ void __launch_bounds__(AB) k_mlp(
    const float* __restrict__ fps, const float* __restrict__ W1,
    const float* __restrict__ b1,  const float* __restrict__ W2,
    const float* __restrict__ b2,  const float* __restrict__ W3,
    const float* __restrict__ b3,  const int* __restrict__ idx,
    float* __restrict__ energy)
{
    __shared__ float sW1[E_ * P_ * H_];   // 2400 floats
    __shared__ float sB1[E_ * H_];
    __shared__ float sW2[E_ * H_ * H_];   // 1200 floats
    __shared__ float sB2[E_ * H_];
    __shared__ float sW3[E_ * H_];
    __shared__ float sB3[E_];
    __shared__ int   skey[AB];

    int t = threadIdx.x;
    for (int i = t; i < E_ * P_ * H_; i += AB) sW1[i] = W1[i];
    for (int i = t; i < E_ * H_;      i += AB) sB1[i] = b1[i];
    for (int i = t; i < E_ * H_ * H_; i += AB) sW2[i] = W2[i];
    for (int i = t; i < E_ * H_;      i += AB) sB2[i] = b2[i];
    for (int i = t; i < E_ * H_;      i += AB) sW3[i] = W3[i];
    if (t < E_) sB3[t] = b3[t];

    int a = blockIdx.x * AB + t;
    int key = (a < Q_) ? idx[a] : -1;
    skey[t] = key;
    __syncthreads();
    if (a >= Q_) return;

    // stable local rank: # of earlier atoms in this block with the same key
    int lr = 0;
    #pragma unroll 1
    for (int j = 0; j < t; j++) lr += (skey[j] == key);
    int pos = g_key_base[key] + g_hist[(size_t)key * NB + blockIdx.x] + lr;

    int e = a / QE_;
    const float* w1 = sW1 + e * P_ * H_;
    const float* w2 = sW2 + e * H_ * H_;
    const float* w3 = sW3 + e * H_;

    // layer 1 pre-activation accumulators (registers: unrolled-index only)
    float h1[H_];
    #pragma unroll
    for (int h = 0; h < H_; h++) h1[h] = sB1[e * H_ + h];

    const float* xrow = fps + (size_t)a * P_;
    #pragma unroll 4
    for (int p = 0; p < P_; p++) {          // rolled over p: x is streamed
        float xp = xrow[p];
        const float* w1p = w1 + p * H_;
        #pragma unroll
        for (int h = 0; h < H_; h++) h1[h] = fmaf(xp, w1p[h], h1[h]);
    }
    #pragma unroll
    for (int h = 0; h < H_; h++) h1[h] = tanhf(h1[h]);

    // layer 2: h2 = tanh(h1 @ W2 + b2)   (g2 reuses the same registers)
    float g2[H_];
    #pragma unroll
    for (int j = 0; j < H_; j++) {
        float s = sB2[e * H_ + j];
        #pragma unroll
        for (int h = 0; h < H_; h++) s = fmaf(h1[h], w2[h * H_ + j], s);
        g2[j] = tanhf(s);
    }

    // layer 3 forward + seed backward: g2[j] <- w3[j] * (1 - h2[j]^2)
    float en = sB3[e];
    #pragma unroll
    for (int j = 0; j < H_; j++) {
        float v = g2[j];
        en = fmaf(v, w3[j], en);
        g2[j] = w3[j] * (1.0f - v * v);
    }
    atomicAdd(&energy[key], en);

    // g1 = (W2 @ g2) * (1 - h1^2)
    float g1[H_];
    #pragma unroll
    for (int h = 0; h < H_; h++) {
        float s = 0.0f;
        #pragma unroll
        for (int j = 0; j < H_; j++) s = fmaf(w2[h * H_ + j], g2[j], s);
        g1[h] = s * (1.0f - h1[h] * h1[h]);
    }

    // dE/dx = W1 @ g1, streamed out into SORTED position (rolled over p)
    float* dst = g_dE + (size_t)pos * P_;
    #pragma unroll 4
    for (int p = 0; p < P_; p++) {
        const float* w1p = w1 + p * H_;
        float s = 0.0f;
        #pragma unroll
        for (int h = 0; h < H_; h++) s = fmaf(w1p[h], g1[h], s);
        dst[p] = s;
    }
}

// ---------------------------------------------------------------------------
// Sparse COO transpose-matvec: force[col] -= val * dE_sorted[row]
// Vectorized x4 loads (NNZ divisible by 4). dE + force live in L2.
// ---------------------------------------------------------------------------
__global__ void k_scatter(const int4* __restrict__ rows,
                          const int4* __restrict__ cols,
                          const float4* __restrict__ vals,
                          float* __restrict__ force)
{
    int i = blockIdx.x * blockDim.x + threadIdx.x;
    if (i >= NNZ_ / 4) return;
    int4   r = rows[i];
    int4   c = cols[i];
    float4 v = vals[i];
    float d0 = __ldg(&g_dE[r.x]);
    float d1 = __ldg(&g_dE[r.y]);
    float d2 = __ldg(&g_dE[r.z]);
    float d3 = __ldg(&g_dE[r.w]);
    atomicAdd(&force[c.x], -v.x * d0);
    atomicAdd(&force[c.y], -v.y * d1);
    atomicAdd(&force[c.z], -v.z * d2);
    atomicAdd(&force[c.w], -v.w * d3);
}

// ---------------------------------------------------------------------------
extern "C" void kernel_launch(void* const* d_in, const int* in_sizes, int n_in,
                              void* d_out, int out_size)
{
    const float* fps       = (const float*)d_in[0];
    const float* W1        = (const float*)d_in[1];
    const float* b1        = (const float*)d_in[2];
    const float* W2        = (const float*)d_in[3];
    const float* b2        = (const float*)d_in[4];
    const float* W3        = (const float*)d_in[5];
    const float* b3        = (const float*)d_in[6];
    const int*   image_idx = (const int*)d_in[7];
    const int*   fp_rows   = (const int*)d_in[8];
    const int*   fp_cols   = (const int*)d_in[9];
    const float* fp_vals   = (const float*)d_in[10];

    float* out    = (float*)d_out;
    float* energy = out;               // [NIMG, 1]
    float* force  = out + NIMG_;       // [Q, 3] flattened

    // zero the whole output (atomically accumulated)
    k_zero<<<(out_size + 255) / 256, 256>>>(out, out_size);

    // stable counting-sort machinery for argsort(image_idx)
    k_hist<<<NB, AB>>>(image_idx);
    k_scan_blocks<<<NIMG_, 1024>>>();
    k_scan_keys<<<1, 1024>>>();

    // fused MLP fwd/bwd + energy scatter + sorted dE write
    k_mlp<<<NB, AB>>>(fps, W1, b1, W2, b2, W3, b3, image_idx, energy);

    // sparse force accumulation
    k_scatter<<<(NNZ_ / 4 + 255) / 256, 256>>>(
        (const int4*)fp_rows, (const int4*)fp_cols, (const float4*)fp_vals, force);
}

// round 3
// speedup vs baseline: 1.0894x; 1.0894x over previous
#include <cuda_runtime.h>

// Problem constants (fixed shapes from reference_code)
#define E_    3
#define QE_   60000
#define P_    40
#define H_    20
#define NIMG_ 1800
#define Q_    (E_ * QE_)        // 180000 atoms
#define NNZ_  14400000
#define AB    256               // atoms per block
#define NB    704               // ceil(Q_/AB)

// Scratch (static device globals — sanctioned)
__device__ float g_dE[(size_t)Q_ * P_];        // NEGATED dE/dFP, sorted order, 28.8 MB
__device__ int   g_hist[(size_t)NIMG_ * NB];
__device__ int   g_key_total[NIMG_];
__device__ int   g_key_base[NIMG_];

__device__ __forceinline__ float tanh_fast(float x) {
    float y;
    asm("tanh.approx.f32 %0, %1;" : "=f"(y) : "f"(x));
    return y;
}

// ---------------------------------------------------------------------------
__global__ void k_zero(float* __restrict__ out, int n) {
    int i = blockIdx.x * blockDim.x + threadIdx.x;
    if (i < n) out[i] = 0.0f;
}

// ---------------------------------------------------------------------------
__global__ void k_hist(const int* __restrict__ idx) {
    __shared__ int h[NIMG_];
    for (int k = threadIdx.x; k < NIMG_; k += blockDim.x) h[k] = 0;
    __syncthreads();
    int a = blockIdx.x * AB + threadIdx.x;
    if (a < Q_) atomicAdd(&h[idx[a]], 1);
    __syncthreads();
    for (int k = threadIdx.x; k < NIMG_; k += blockDim.x)
        g_hist[(size_t)k * NB + blockIdx.x] = h[k];
}

// ---------------------------------------------------------------------------
// Per-key exclusive scan over blocks: warp-shuffle 2-level scan, 2 barriers.
// grid = NIMG_, block = 1024 (32 warps; NB=704 <= 1024).
// ---------------------------------------------------------------------------
__global__ void k_scan_blocks() {
    __shared__ int wsum[32];
    int k = blockIdx.x, t = threadIdx.x;
    int lane = t & 31, w = t >> 5;
    int v = (t < NB) ? g_hist[(size_t)k * NB + t] : 0;
    int s = v;
    #pragma unroll
    for (int o = 1; o < 32; o <<= 1) {
        int x = __shfl_up_sync(0xFFFFFFFFu, s, o);
        if (lane >= o) s += x;
    }
    if (lane == 31) wsum[w] = s;
    __syncthreads();
    if (w == 0) {
        int ws = wsum[lane];
        #pragma unroll
        for (int o = 1; o < 32; o <<= 1) {
            int x = __shfl_up_sync(0xFFFFFFFFu, ws, o);
            if (lane >= o) ws += x;
        }
        wsum[lane] = ws;
    }
    __syncthreads();
    int incl = ((w > 0) ? wsum[w - 1] : 0) + s;
    if (t < NB) g_hist[(size_t)k * NB + t] = incl - v;   // exclusive
    if (t == NB - 1) g_key_total[k] = incl;
}

// ---------------------------------------------------------------------------
// Exclusive scan over 1800 key totals (2 elems/thread, shuffle scan).
// ---------------------------------------------------------------------------
__global__ void k_scan_keys() {
    __shared__ int wsum[32];
    int t = threadIdx.x, lane = t & 31, w = t >> 5;
    int i0 = 2 * t, i1 = 2 * t + 1;
    int v0 = (i0 < NIMG_) ? g_key_total[i0] : 0;
    int v1 = (i1 < NIMG_) ? g_key_total[i1] : 0;
    int p = v0 + v1, s = p;
    #pragma unroll
    for (int o = 1; o < 32; o <<= 1) {
        int x = __shfl_up_sync(0xFFFFFFFFu, s, o);
        if (lane >= o) s += x;
    }
    if (lane == 31) wsum[w] = s;
    __syncthreads();
    if (w == 0) {
        int ws = wsum[lane];
        #pragma unroll
        for (int o = 1; o < 32; o <<= 1) {
            int x = __shfl_up_sync(0xFFFFFFFFu, ws, o);
            if (lane >= o) ws += x;
        }
        wsum[lane] = ws;
    }
    __syncthreads();
    int excl = ((w > 0) ? wsum[w - 1] : 0) + s - p;
    if (i0 < NIMG_) g_key_base[i0] = excl;
    if (i1 < NIMG_) g_key_base[i1] = excl + v0;
}

// ---------------------------------------------------------------------------
// Fused: stable rank + MLP fwd + input-grad + energy scatter.
// h1/g2/g1 (20 floats each) indexed ONLY in fully-unrolled loops -> registers.
// fps read and dE written as float4 (10 LDG.128 / 10 STG.128 per atom).
// dE stored NEGATED so k_scatter is a pure fma+RED.
// ---------------------------------------------------------------------------
__global__ void __launch_bounds__(AB) k_mlp(
    const float* __restrict__ fps, const float* __restrict__ W1,
    const float* __restrict__ b1,  const float* __restrict__ W2,
    const float* __restrict__ b2,  const float* __restrict__ W3,
    const float* __restrict__ b3,  const int* __restrict__ idx,
    float* __restrict__ energy)
{
    __shared__ float sW1[E_ * P_ * H_];
    __shared__ float sB1[E_ * H_];
    __shared__ float sW2[E_ * H_ * H_];
    __shared__ float sB2[E_ * H_];
    __shared__ float sW3[E_ * H_];
    __shared__ float sB3[E_];
    __shared__ int   skey[AB];

    int t = threadIdx.x;
    for (int i = t; i < E_ * P_ * H_; i += AB) sW1[i] = W1[i];
    for (int i = t; i < E_ * H_;      i += AB) sB1[i] = b1[i];
    for (int i = t; i < E_ * H_ * H_; i += AB) sW2[i] = W2[i];
    for (int i = t; i < E_ * H_;      i += AB) sB2[i] = b2[i];
    for (int i = t; i < E_ * H_;      i += AB) sW3[i] = W3[i];
    if (t < E_) sB3[t] = b3[t];

    int a = blockIdx.x * AB + t;
    int key = (a < Q_) ? idx[a] : -1;
    skey[t] = key;
    __syncthreads();
    if (a >= Q_) return;

    // stable local rank among same-key threads of this block
    int lr = 0;
    #pragma unroll 1
    for (int j = 0; j < t; j++) lr += (skey[j] == key);
    int pos = g_key_base[key] + g_hist[(size_t)key * NB + blockIdx.x] + lr;

    int e = a / QE_;
    const float* w1 = sW1 + e * P_ * H_;
    const float* w2 = sW2 + e * H_ * H_;
    const float* w3 = sW3 + e * H_;

    float h1[H_];
    #pragma unroll
    for (int h = 0; h < H_; h++) h1[h] = sB1[e * H_ + h];

    // layer 1: stream x as float4 (rolled outer loop, unrolled inner)
    const float4* xrow = (const float4*)(fps + (size_t)a * P_);
    #pragma unroll 2
    for (int p4 = 0; p4 < P_ / 4; p4++) {
        float4 x = xrow[p4];
        const float* w1p = w1 + p4 * 4 * H_;
        #pragma unroll
        for (int h = 0; h < H_; h++) {
            float s = fmaf(x.x, w1p[h], h1[h]);
            s = fmaf(x.y, w1p[H_ + h], s);
            s = fmaf(x.z, w1p[2 * H_ + h], s);
            h1[h] = fmaf(x.w, w1p[3 * H_ + h], s);
        }
    }
    #pragma unroll
    for (int h = 0; h < H_; h++) h1[h] = tanh_fast(h1[h]);

    // layer 2
    float g2[H_];
    #pragma unroll
    for (int j = 0; j < H_; j++) {
        float s = sB2[e * H_ + j];
        #pragma unroll
        for (int h = 0; h < H_; h++) s = fmaf(h1[h], w2[h * H_ + j], s);
        g2[j] = tanh_fast(s);
    }

    // layer 3 fwd + backward seed
    float en = sB3[e];
    #pragma unroll
    for (int j = 0; j < H_; j++) {
        float v = g2[j];
        en = fmaf(v, w3[j], en);
        g2[j] = w3[j] * (1.0f - v * v);
    }
    atomicAdd(&energy[key], en);

    // g1 = (W2 @ g2) * (1 - h1^2)
    float g1[H_];
    #pragma unroll
    for (int h = 0; h < H_; h++) {
        float s = 0.0f;
        #pragma unroll
        for (int j = 0; j < H_; j++) s = fmaf(w2[h * H_ + j], g2[j], s);
        g1[h] = s * (1.0f - h1[h] * h1[h]);
    }

    // -dE/dx = -(W1 @ g1), float4 stores into sorted position
    float4* dst = (float4*)(g_dE + (size_t)pos * P_);
    #pragma unroll 2
    for (int p4 = 0; p4 < P_ / 4; p4++) {
        const float* w1p = w1 + p4 * 4 * H_;
        float4 o;
        float s0 = 0, s1 = 0, s2 = 0, s3 = 0;
        #pragma unroll
        for (int h = 0; h < H_; h++) {
            s0 = fmaf(w1p[h],          g1[h], s0);
            s1 = fmaf(w1p[H_ + h],     g1[h], s1);
            s2 = fmaf(w1p[2 * H_ + h], g1[h], s2);
            s3 = fmaf(w1p[3 * H_ + h], g1[h], s3);
        }
        o.x = -s0; o.y = -s1; o.z = -s2; o.w = -s3;
        dst[p4] = o;
    }
}

// ---------------------------------------------------------------------------
// Sparse COO transpose-matvec: force[col] += val * (-dE_sorted[row])
// COO streams use __ldcs (evict-streaming) so the 172.8 MB of rows/cols/vals
// do NOT thrash L2; g_dE (28.8 MB) and force (2.2 MB) stay L2-resident.
// ---------------------------------------------------------------------------
__global__ void k_scatter(const int4* __restrict__ rows,
                          const int4* __restrict__ cols,
                          const float4* __restrict__ vals,
                          float* __restrict__ force)
{
    int i = blockIdx.x * blockDim.x + threadIdx.x;
    if (i >= NNZ_ / 4) return;
    int4   r = __ldcs(&rows[i]);
    int4   c = __ldcs(&cols[i]);
    float4 v = __ldcs(&vals[i]);
    float d0 = __ldg(&g_dE[r.x]);
    float d1 = __ldg(&g_dE[r.y]);
    float d2 = __ldg(&g_dE[r.z]);
    float d3 = __ldg(&g_dE[r.w]);
    atomicAdd(&force[c.x], v.x * d0);
    atomicAdd(&force[c.y], v.y * d1);
    atomicAdd(&force[c.z], v.z * d2);
    atomicAdd(&force[c.w], v.w * d3);
}

// ---------------------------------------------------------------------------
extern "C" void kernel_launch(void* const* d_in, const int* in_sizes, int n_in,
                              void* d_out, int out_size)
{
    const float* fps       = (const float*)d_in[0];
    const float* W1        = (const float*)d_in[1];
    const float* b1        = (const float*)d_in[2];
    const float* W2        = (const float*)d_in[3];
    const float* b2        = (const float*)d_in[4];
    const float* W3        = (const float*)d_in[5];
    const float* b3        = (const float*)d_in[6];
    const int*   image_idx = (const int*)d_in[7];
    const int*   fp_rows   = (const int*)d_in[8];
    const int*   fp_cols   = (const int*)d_in[9];
    const float* fp_vals   = (const float*)d_in[10];

    float* out    = (float*)d_out;
    float* energy = out;               // [NIMG, 1]
    float* force  = out + NIMG_;       // [Q, 3] flattened

    k_zero<<<(out_size + 255) / 256, 256>>>(out, out_size);

    k_hist<<<NB, AB>>>(image_idx);
    k_scan_blocks<<<NIMG_, 1024>>>();
    k_scan_keys<<<1, 1024>>>();

    k_mlp<<<NB, AB>>>(fps, W1, b1, W2, b2, W3, b3, image_idx, energy);

    k_scatter<<<(NNZ_ / 4 + 255) / 256, 256>>>(
        (const int4*)fp_rows, (const int4*)fp_cols, (const float4*)fp_vals, force);
}